// round 5
// baseline (speedup 1.0000x reference)
#include <cuda_runtime.h>
#include <cuda_bf16.h>
#include <cstdint>

// ============================================================
// Problem constants
// ============================================================
#define NUM_E     8
#define DIM_H     1024
#define DIM_F     4096
#define TOK_TOTAL 16384
#define TOK_PER_E 2048

// GEMM tiling: CTA 128x128, 8 warps of 64x32, 3-stage pipeline, 2 CTA/SM
#define STAGES  3
#define KT      32             // k elements per stage
#define MT      128
#define NT      128

#define A_STRIDE        36     // floats per smem row (32 data + 4 pad) -> conflict-free
#define A_STAGE_FLOATS  (MT * A_STRIDE)          // 4608
#define B_STAGE_FLOATS  (NT * A_STRIDE)          // 4608
#define STAGE_FLOATS    (A_STAGE_FLOATS + B_STAGE_FLOATS)
#define SMEM_ALLOC      (STAGES * STAGE_FLOATS * 4)   // 110592 bytes

// ============================================================
// Scratch (__device__ globals — allocation-free rule)
// ============================================================
__device__ float g_xt[(size_t)TOK_TOTAL * DIM_H];          //  64 MB  x, tf32-rounded
__device__ float g_w1t[(size_t)NUM_E * DIM_F * DIM_H];     // 128 MB  w1^T [e][f][h]
__device__ float g_w2t[(size_t)NUM_E * DIM_H * DIM_F];     // 128 MB  w2^T [e][h][f]
__device__ float g_inter[(size_t)TOK_TOTAL * DIM_F];       // 256 MB  gelu(x@w1), tf32-rounded

// ============================================================
// Helpers (baseline PTX only — no tcgen05 on this toolchain)
// ============================================================
__device__ __forceinline__ uint32_t smem_to_u32(const void* smem_ptr) {
    uint32_t addr;
    asm("{ .reg .u64 tmp; cvta.to.shared.u64 tmp, %1; cvt.u32.u64 %0, tmp; }"
        : "=r"(addr) : "l"(smem_ptr));
    return addr;
}

// round-to-nearest fp32 -> tf32 (kept in fp32 container, low mantissa zeroed)
__device__ __forceinline__ float rn_tf32(float x) {
    uint32_t u;
    asm("cvt.rna.tf32.f32 %0, %1;" : "=r"(u) : "f"(x));
    return __uint_as_float(u);
}

__device__ __forceinline__ void cp_async16(uint32_t smem_addr, const void* gptr) {
    asm volatile("cp.async.cg.shared.global [%0], [%1], 16;"
                 :: "r"(smem_addr), "l"(gptr));
}
#define CP_ASYNC_COMMIT() asm volatile("cp.async.commit_group;" ::: "memory")
template <int N>
__device__ __forceinline__ void cp_async_wait_group() {
    asm volatile("cp.async.wait_group %0;" :: "n"(N) : "memory");
}

// mma.sync m16n8k8 tf32, row.col, f32 accumulate (sm_80+ baseline PTX)
__device__ __forceinline__ void mma_tf32(float (&d)[4],
                                         const uint32_t (&a)[4],
                                         const uint32_t (&b)[2]) {
    asm volatile(
        "mma.sync.aligned.m16n8k8.row.col.f32.tf32.tf32.f32 "
        "{%0,%1,%2,%3}, {%4,%5,%6,%7}, {%8,%9}, {%0,%1,%2,%3};"
        : "+f"(d[0]), "+f"(d[1]), "+f"(d[2]), "+f"(d[3])
        : "r"(a[0]), "r"(a[1]), "r"(a[2]), "r"(a[3]),
          "r"(b[0]), "r"(b[1]));
}

__device__ __forceinline__ float gelu_tanh(float x) {
    float x3 = x * x * x;
    float t  = tanhf(0.7978845608028654f * (x + 0.044715f * x3));
    return 0.5f * x * (1.0f + t);
}

// ============================================================
// Prep kernels
// ============================================================
__global__ void convert_rn_kernel(const float* __restrict__ in, float* __restrict__ out, int n)
{
    for (int i = blockIdx.x * blockDim.x + threadIdx.x; i < n; i += gridDim.x * blockDim.x)
        out[i] = rn_tf32(in[i]);
}

// in: [E][R][C] -> out: [E][C][R], with RN-to-tf32 conversion.
__global__ void transpose_rn_kernel(const float* __restrict__ in, float* __restrict__ out,
                                    int R, int C)
{
    __shared__ float tile[32][33];
    const int e  = blockIdx.z;
    const int c0 = blockIdx.x << 5;
    const int r0 = blockIdx.y << 5;
    const float* ine  = in  + (size_t)e * R * C;
    float*       oute = out + (size_t)e * R * C;
    const int tx = threadIdx.x, ty = threadIdx.y;   // 32 x 8
#pragma unroll
    for (int dy = 0; dy < 32; dy += 8)
        tile[ty + dy][tx] = ine[(size_t)(r0 + ty + dy) * C + c0 + tx];
    __syncthreads();
#pragma unroll
    for (int dy = 0; dy < 32; dy += 8)
        oute[(size_t)(c0 + ty + dy) * R + r0 + tx] = rn_tf32(tile[tx][ty + dy]);
}

// ============================================================
// Grouped tf32 GEMM:  C[e] (+gelu) = A[e] @ B[e]^T
//   A: [Mtot, K] K-major tf32-in-fp32;  B: [Ntot, K] K-major tf32-in-fp32
// CTA: 128x128 tile, 8 warps of 64x32, 3-stage cp.async pipeline, 2 CTA/SM,
// register double-buffered fragments across k-slices.
// ============================================================
__global__ void __launch_bounds__(256, 2) gemm_tf32_kernel(
    const float* __restrict__ A, int lda, long sAe,
    const float* __restrict__ B, int ldb, long sBe,
    float* __restrict__ C, int ldc, long sCe,
    int K, int n_tiles, int do_gelu)
{
    extern __shared__ float smemf[];

    const int tid = threadIdx.x;
    const int wid = tid >> 5;
    const int lid = tid & 31;
    const int g   = lid >> 2;      // groupID (0..7)
    const int tig = lid & 3;       // thread in group (0..3)
    const int wm  = (wid & 1) * 64;      // 2 warps across M
    const int wn  = (wid >> 1) * 32;     // 4 warps across N

    const int e  = blockIdx.y;
    const int mt = blockIdx.x / n_tiles;
    const int nt = blockIdx.x - mt * n_tiles;

    const float* Ab = A + (size_t)e * sAe + (size_t)mt * MT * lda;
    const float* Bb = B + (size_t)e * sBe + (size_t)nt * NT * ldb;
    float*       Cb = C + (size_t)e * sCe + (size_t)mt * MT * ldc + (size_t)nt * NT;

    float acc[4][4][4];                  // [mfrag][nfrag][quad]
#pragma unroll
    for (int f = 0; f < 4; f++)
#pragma unroll
        for (int j = 0; j < 4; j++)
#pragma unroll
            for (int q = 0; q < 4; q++) acc[f][j][q] = 0.0f;

    // ---------------- stage loader ----------------
    auto load_stage = [&](int buf, int k0) {
        float* as_ = smemf + buf * STAGE_FLOATS;
        // A: 128 rows x 32 floats = 1024 16B chunks, 4 per thread
#pragma unroll
        for (int t = 0; t < 4; t++) {
            int idx = tid + t * 256;
            int r = idx >> 3, c = idx & 7;
            cp_async16(smem_to_u32(as_ + r * A_STRIDE + c * 4),
                       Ab + (size_t)r * lda + k0 + c * 4);
        }
        float* bs_ = as_ + A_STAGE_FLOATS;
        // B: 128 rows x 32 floats = 1024 chunks, 4 per thread
#pragma unroll
        for (int t = 0; t < 4; t++) {
            int idx = tid + t * 256;
            int r = idx >> 3, c = idx & 7;
            cp_async16(smem_to_u32(bs_ + r * A_STRIDE + c * 4),
                       Bb + (size_t)r * ldb + k0 + c * 4);
        }
    };

    const int NK = K / KT;

    // prologue: fill stages 0..STAGES-2
#pragma unroll
    for (int s = 0; s < STAGES - 1; s++) {
        load_stage(s, s * KT);
        CP_ASYNC_COMMIT();
    }

    uint32_t a[2][4][4];
    uint32_t b[2][4][2];

    int buf = 0;
    for (int i = 0; i < NK; i++) {
        cp_async_wait_group<STAGES - 2>();
        __syncthreads();

        // issue next stage's gmem loads into the buffer consumed last iteration
        const int jn = i + STAGES - 1;
        int nbuf = buf + 1; if (nbuf == STAGES) nbuf = 0;
        if (jn < NK) {
            int lbuf = buf - 1; if (lbuf < 0) lbuf += STAGES;
            load_stage(lbuf, jn * KT);
        }
        CP_ASYNC_COMMIT();

        // compute on stage `buf` with register double-buffered fragments
        const float* As = smemf + buf * STAGE_FLOATS;
        const float* Bs = As + A_STAGE_FLOATS;

        auto load_frags = [&](int s, int kk) {
            const int k0 = kk * 8 + tig;
#pragma unroll
            for (int f = 0; f < 4; f++) {
                const float* ap = As + (wm + 16 * f + g) * A_STRIDE + k0;
                a[s][f][0] = __float_as_uint(ap[0]);
                a[s][f][1] = __float_as_uint(ap[8 * A_STRIDE]);
                a[s][f][2] = __float_as_uint(ap[4]);
                a[s][f][3] = __float_as_uint(ap[8 * A_STRIDE + 4]);
            }
#pragma unroll
            for (int j = 0; j < 4; j++) {
                const float* bp = Bs + (wn + 8 * j + g) * A_STRIDE + k0;
                b[s][j][0] = __float_as_uint(bp[0]);
                b[s][j][1] = __float_as_uint(bp[4]);
            }
        };

        load_frags(0, 0);
#pragma unroll
        for (int kk = 0; kk < KT / 8; kk++) {
            if (kk < KT / 8 - 1)
                load_frags((kk + 1) & 1, kk + 1);   // prefetch next k-slice
            const int cur = kk & 1;
#pragma unroll
            for (int f = 0; f < 4; f++)
#pragma unroll
                for (int j = 0; j < 4; j++)
                    mma_tf32(acc[f][j], a[cur][f], b[cur][j]);
        }
        buf = nbuf;
    }

    // ---------------- epilogue ----------------
#pragma unroll
    for (int f = 0; f < 4; f++) {
        const int r0 = wm + 16 * f + g;
        const int r1 = r0 + 8;
#pragma unroll
        for (int j = 0; j < 4; j++) {
            const int col = wn + 8 * j + 2 * tig;
            float v0 = acc[f][j][0], v1 = acc[f][j][1];
            float v2 = acc[f][j][2], v3 = acc[f][j][3];
            if (do_gelu) {
                v0 = rn_tf32(gelu_tanh(v0));
                v1 = rn_tf32(gelu_tanh(v1));
                v2 = rn_tf32(gelu_tanh(v2));
                v3 = rn_tf32(gelu_tanh(v3));
            }
            *reinterpret_cast<float2*>(Cb + (size_t)r0 * ldc + col) = make_float2(v0, v1);
            *reinterpret_cast<float2*>(Cb + (size_t)r1 * ldc + col) = make_float2(v2, v3);
        }
    }
}

// ============================================================
// Host launcher
// ============================================================
extern "C" void kernel_launch(void* const* d_in, const int* in_sizes, int n_in,
                              void* d_out, int out_size)
{
    const float* x  = (const float*)d_in[0];
    const float* w1 = (const float*)d_in[1];
    const float* w2 = (const float*)d_in[2];
    float* out = (float*)d_out;

    float *xt, *w1t, *w2t, *inter;
    cudaGetSymbolAddress((void**)&xt,    g_xt);
    cudaGetSymbolAddress((void**)&w1t,   g_w1t);
    cudaGetSymbolAddress((void**)&w2t,   g_w2t);
    cudaGetSymbolAddress((void**)&inter, g_inter);

    cudaFuncSetAttribute(gemm_tf32_kernel,
                         cudaFuncAttributeMaxDynamicSharedMemorySize, SMEM_ALLOC);

    // prep: RN tf32 conversion + weight transposes to K-major
    convert_rn_kernel<<<2048, 256>>>(x, xt, TOK_TOTAL * DIM_H);
    transpose_rn_kernel<<<dim3(DIM_F / 32, DIM_H / 32, NUM_E), dim3(32, 8)>>>(
        w1, w1t, DIM_H, DIM_F);   // [E][H][F] -> [E][F][H]
    transpose_rn_kernel<<<dim3(DIM_H / 32, DIM_F / 32, NUM_E), dim3(32, 8)>>>(
        w2, w2t, DIM_F, DIM_H);   // [E][F][H] -> [E][H][F]

    // GEMM1: inter = gelu(x @ w1^T_kmajor)   (M=2048/expert, N=4096, K=1024)
    gemm_tf32_kernel<<<dim3((TOK_PER_E / MT) * (DIM_F / NT), NUM_E), 256, SMEM_ALLOC>>>(
        xt,    DIM_H, (long)TOK_PER_E * DIM_H,
        w1t,   DIM_H, (long)DIM_F * DIM_H,
        inter, DIM_F, (long)TOK_PER_E * DIM_F,
        DIM_H, DIM_F / NT, /*gelu=*/1);

    // GEMM2: out = inter @ w2^T_kmajor       (M=2048/expert, N=1024, K=4096)
    gemm_tf32_kernel<<<dim3((TOK_PER_E / MT) * (DIM_H / NT), NUM_E), 256, SMEM_ALLOC>>>(
        inter, DIM_F, (long)TOK_PER_E * DIM_F,
        w2t,   DIM_F, (long)DIM_H * DIM_F,
        out,   DIM_H, (long)TOK_PER_E * DIM_H,
        DIM_F, DIM_H / NT, /*gelu=*/0);
}

// round 6
// speedup vs baseline: 1.0316x; 1.0316x over previous
#include <cuda_runtime.h>
#include <cuda_bf16.h>
#include <cstdint>

// ============================================================
// Problem constants
// ============================================================
#define NUM_E     8
#define DIM_H     1024
#define DIM_F     4096
#define TOK_TOTAL 16384
#define TOK_PER_E 2048

// GEMM tiling: CTA 128x128, 8 warps of 64x32, 3-stage pipeline, 2 CTA/SM
#define STAGES  3
#define KT      32             // k elements per stage
#define MT      128
#define NT      128

#define A_STRIDE        36     // floats per smem row (32 data + 4 pad) -> conflict-free
#define A_STAGE_FLOATS  (MT * A_STRIDE)          // 4608
#define B_STAGE_FLOATS  (NT * A_STRIDE)          // 4608
#define STAGE_FLOATS    (A_STAGE_FLOATS + B_STAGE_FLOATS)
#define SMEM_ALLOC      (STAGES * STAGE_FLOATS * 4)   // 110592 bytes

// ============================================================
// Scratch (__device__ globals — allocation-free rule)
// ============================================================
__device__ float g_xt[(size_t)TOK_TOTAL * DIM_H];          //  64 MB  x, tf32-rounded
__device__ float g_w1t[(size_t)NUM_E * DIM_F * DIM_H];     // 128 MB  w1^T [e][f][h]
__device__ float g_w2t[(size_t)NUM_E * DIM_H * DIM_F];     // 128 MB  w2^T [e][h][f]
__device__ float g_inter[(size_t)TOK_TOTAL * DIM_F];       // 256 MB  gelu(x@w1), tf32-rounded

// ============================================================
// Helpers (baseline PTX only — no tcgen05 on this toolchain)
// ============================================================
__device__ __forceinline__ uint32_t smem_to_u32(const void* smem_ptr) {
    uint32_t addr;
    asm("{ .reg .u64 tmp; cvta.to.shared.u64 tmp, %1; cvt.u32.u64 %0, tmp; }"
        : "=r"(addr) : "l"(smem_ptr));
    return addr;
}

// round-to-nearest fp32 -> tf32 (kept in fp32 container, low mantissa zeroed)
__device__ __forceinline__ float rn_tf32(float x) {
    uint32_t u;
    asm("cvt.rna.tf32.f32 %0, %1;" : "=r"(u) : "f"(x));
    return __uint_as_float(u);
}

__device__ __forceinline__ void cp_async16(uint32_t smem_addr, const void* gptr) {
    asm volatile("cp.async.cg.shared.global [%0], [%1], 16;"
                 :: "r"(smem_addr), "l"(gptr));
}
#define CP_ASYNC_COMMIT() asm volatile("cp.async.commit_group;" ::: "memory")
template <int N>
__device__ __forceinline__ void cp_async_wait_group() {
    asm volatile("cp.async.wait_group %0;" :: "n"(N) : "memory");
}

// mma.sync m16n8k8 tf32, row.col, f32 accumulate (sm_80+ baseline PTX)
__device__ __forceinline__ void mma_tf32(float (&d)[4],
                                         const uint32_t (&a)[4],
                                         const uint32_t (&b)[2]) {
    asm volatile(
        "mma.sync.aligned.m16n8k8.row.col.f32.tf32.tf32.f32 "
        "{%0,%1,%2,%3}, {%4,%5,%6,%7}, {%8,%9}, {%0,%1,%2,%3};"
        : "+f"(d[0]), "+f"(d[1]), "+f"(d[2]), "+f"(d[3])
        : "r"(a[0]), "r"(a[1]), "r"(a[2]), "r"(a[3]),
          "r"(b[0]), "r"(b[1]));
}

__device__ __forceinline__ float gelu_tanh(float x) {
    float x3 = x * x * x;
    float t  = tanhf(0.7978845608028654f * (x + 0.044715f * x3));
    return 0.5f * x * (1.0f + t);
}

// ============================================================
// Prep kernels
// ============================================================
__global__ void convert_rn_kernel(const float* __restrict__ in, float* __restrict__ out, int n)
{
    for (int i = blockIdx.x * blockDim.x + threadIdx.x; i < n; i += gridDim.x * blockDim.x)
        out[i] = rn_tf32(in[i]);
}

// in: [E][R][C] -> out: [E][C][R], with RN-to-tf32 conversion.
__global__ void transpose_rn_kernel(const float* __restrict__ in, float* __restrict__ out,
                                    int R, int C)
{
    __shared__ float tile[32][33];
    const int e  = blockIdx.z;
    const int c0 = blockIdx.x << 5;
    const int r0 = blockIdx.y << 5;
    const float* ine  = in  + (size_t)e * R * C;
    float*       oute = out + (size_t)e * R * C;
    const int tx = threadIdx.x, ty = threadIdx.y;   // 32 x 8
#pragma unroll
    for (int dy = 0; dy < 32; dy += 8)
        tile[ty + dy][tx] = ine[(size_t)(r0 + ty + dy) * C + c0 + tx];
    __syncthreads();
#pragma unroll
    for (int dy = 0; dy < 32; dy += 8)
        oute[(size_t)(c0 + ty + dy) * R + r0 + tx] = rn_tf32(tile[tx][ty + dy]);
}

// ============================================================
// Grouped tf32 GEMM:  C[e] (+gelu) = A[e] @ B[e]^T
//   A: [Mtot, K] K-major tf32-in-fp32;  B: [Ntot, K] K-major tf32-in-fp32
// CTA: 128x128 tile, 8 warps of 64x32, 3-stage cp.async pipeline, 2 CTA/SM,
// per-warp phase-staggered k-slice order (keeps tensor pipe fed across SMSP).
// ============================================================
__global__ void __launch_bounds__(256, 2) gemm_tf32_kernel(
    const float* __restrict__ A, int lda, long sAe,
    const float* __restrict__ B, int ldb, long sBe,
    float* __restrict__ C, int ldc, long sCe,
    int K, int n_tiles, int do_gelu)
{
    extern __shared__ float smemf[];

    const int tid = threadIdx.x;
    const int wid = tid >> 5;
    const int lid = tid & 31;
    const int g   = lid >> 2;      // groupID (0..7)
    const int tig = lid & 3;       // thread in group (0..3)
    const int wm  = (wid & 1) * 64;      // 2 warps across M
    const int wn  = (wid >> 1) * 32;     // 4 warps across N

    // phase: warps sharing an SMSP (wid, wid+4) get phases 2 apart;
    // adjacent SMSPs differ by 1 -> de-staggers LDS bursts vs MMA bursts.
    const int phase = ((wid >> 2) << 1) + (wid & 1);

    const int e  = blockIdx.y;
    const int mt = blockIdx.x / n_tiles;
    const int nt = blockIdx.x - mt * n_tiles;

    const float* Ab = A + (size_t)e * sAe + (size_t)mt * MT * lda;
    const float* Bb = B + (size_t)e * sBe + (size_t)nt * NT * ldb;
    float*       Cb = C + (size_t)e * sCe + (size_t)mt * MT * ldc + (size_t)nt * NT;

    float acc[4][4][4];                  // [mfrag][nfrag][quad]
#pragma unroll
    for (int f = 0; f < 4; f++)
#pragma unroll
        for (int j = 0; j < 4; j++)
#pragma unroll
            for (int q = 0; q < 4; q++) acc[f][j][q] = 0.0f;

    // ---------------- stage loader ----------------
    auto load_stage = [&](int buf, int k0) {
        float* as_ = smemf + buf * STAGE_FLOATS;
        // A: 128 rows x 32 floats = 1024 16B chunks, 4 per thread
#pragma unroll
        for (int t = 0; t < 4; t++) {
            int idx = tid + t * 256;
            int r = idx >> 3, c = idx & 7;
            cp_async16(smem_to_u32(as_ + r * A_STRIDE + c * 4),
                       Ab + (size_t)r * lda + k0 + c * 4);
        }
        float* bs_ = as_ + A_STAGE_FLOATS;
        // B: 128 rows x 32 floats = 1024 chunks, 4 per thread
#pragma unroll
        for (int t = 0; t < 4; t++) {
            int idx = tid + t * 256;
            int r = idx >> 3, c = idx & 7;
            cp_async16(smem_to_u32(bs_ + r * A_STRIDE + c * 4),
                       Bb + (size_t)r * ldb + k0 + c * 4);
        }
    };

    const int NK = K / KT;

    // prologue: fill stages 0..STAGES-2
#pragma unroll
    for (int s = 0; s < STAGES - 1; s++) {
        load_stage(s, s * KT);
        CP_ASYNC_COMMIT();
    }

    int buf = 0;
    for (int i = 0; i < NK; i++) {
        cp_async_wait_group<STAGES - 2>();
        __syncthreads();

        // issue next stage's loads into the buffer consumed last iteration
        const int jn = i + STAGES - 1;
        int nbuf = buf + 1; if (nbuf == STAGES) nbuf = 0;
        if (jn < NK) {
            int lbuf = buf - 1; if (lbuf < 0) lbuf += STAGES;
            load_stage(lbuf, jn * KT);
        }
        CP_ASYNC_COMMIT();

        // compute on stage `buf`, k-slices in per-warp rotated order
        const float* As = smemf + buf * STAGE_FLOATS;
        const float* Bs = As + A_STAGE_FLOATS;
#pragma unroll
        for (int kk = 0; kk < KT / 8; kk++) {
            const int kks = (kk + phase) & (KT / 8 - 1);
            const int k0 = kks * 8 + tig;
            uint32_t a[4][4];
#pragma unroll
            for (int f = 0; f < 4; f++) {
                const float* ap = As + (wm + 16 * f + g) * A_STRIDE + k0;
                a[f][0] = __float_as_uint(ap[0]);
                a[f][1] = __float_as_uint(ap[8 * A_STRIDE]);
                a[f][2] = __float_as_uint(ap[4]);
                a[f][3] = __float_as_uint(ap[8 * A_STRIDE + 4]);
            }
            uint32_t b[4][2];
#pragma unroll
            for (int j = 0; j < 4; j++) {
                const float* bp = Bs + (wn + 8 * j + g) * A_STRIDE + k0;
                b[j][0] = __float_as_uint(bp[0]);
                b[j][1] = __float_as_uint(bp[4]);
            }
#pragma unroll
            for (int f = 0; f < 4; f++)
#pragma unroll
                for (int j = 0; j < 4; j++)
                    mma_tf32(acc[f][j], a[f], b[j]);
        }
        buf = nbuf;
    }

    // ---------------- epilogue ----------------
#pragma unroll
    for (int f = 0; f < 4; f++) {
        const int r0 = wm + 16 * f + g;
        const int r1 = r0 + 8;
#pragma unroll
        for (int j = 0; j < 4; j++) {
            const int col = wn + 8 * j + 2 * tig;
            float v0 = acc[f][j][0], v1 = acc[f][j][1];
            float v2 = acc[f][j][2], v3 = acc[f][j][3];
            if (do_gelu) {
                v0 = rn_tf32(gelu_tanh(v0));
                v1 = rn_tf32(gelu_tanh(v1));
                v2 = rn_tf32(gelu_tanh(v2));
                v3 = rn_tf32(gelu_tanh(v3));
            }
            *reinterpret_cast<float2*>(Cb + (size_t)r0 * ldc + col) = make_float2(v0, v1);
            *reinterpret_cast<float2*>(Cb + (size_t)r1 * ldc + col) = make_float2(v2, v3);
        }
    }
}

// ============================================================
// Host launcher
// ============================================================
extern "C" void kernel_launch(void* const* d_in, const int* in_sizes, int n_in,
                              void* d_out, int out_size)
{
    const float* x  = (const float*)d_in[0];
    const float* w1 = (const float*)d_in[1];
    const float* w2 = (const float*)d_in[2];
    float* out = (float*)d_out;

    float *xt, *w1t, *w2t, *inter;
    cudaGetSymbolAddress((void**)&xt,    g_xt);
    cudaGetSymbolAddress((void**)&w1t,   g_w1t);
    cudaGetSymbolAddress((void**)&w2t,   g_w2t);
    cudaGetSymbolAddress((void**)&inter, g_inter);

    cudaFuncSetAttribute(gemm_tf32_kernel,
                         cudaFuncAttributeMaxDynamicSharedMemorySize, SMEM_ALLOC);

    // prep: RN tf32 conversion + weight transposes to K-major
    convert_rn_kernel<<<2048, 256>>>(x, xt, TOK_TOTAL * DIM_H);
    transpose_rn_kernel<<<dim3(DIM_F / 32, DIM_H / 32, NUM_E), dim3(32, 8)>>>(
        w1, w1t, DIM_H, DIM_F);   // [E][H][F] -> [E][F][H]
    transpose_rn_kernel<<<dim3(DIM_H / 32, DIM_F / 32, NUM_E), dim3(32, 8)>>>(
        w2, w2t, DIM_F, DIM_H);   // [E][F][H] -> [E][H][F]

    // GEMM1: inter = gelu(x @ w1^T_kmajor)   (M=2048/expert, N=4096, K=1024)
    gemm_tf32_kernel<<<dim3((TOK_PER_E / MT) * (DIM_F / NT), NUM_E), 256, SMEM_ALLOC>>>(
        xt,    DIM_H, (long)TOK_PER_E * DIM_H,
        w1t,   DIM_H, (long)DIM_F * DIM_H,
        inter, DIM_F, (long)TOK_PER_E * DIM_F,
        DIM_H, DIM_F / NT, /*gelu=*/1);

    // GEMM2: out = inter @ w2^T_kmajor       (M=2048/expert, N=1024, K=4096)
    gemm_tf32_kernel<<<dim3((TOK_PER_E / MT) * (DIM_H / NT), NUM_E), 256, SMEM_ALLOC>>>(
        inter, DIM_F, (long)TOK_PER_E * DIM_F,
        w2t,   DIM_F, (long)DIM_H * DIM_F,
        out,   DIM_H, (long)TOK_PER_E * DIM_H,
        DIM_F, DIM_H / NT, /*gelu=*/0);
}

// round 7
// speedup vs baseline: 1.9336x; 1.8744x over previous
#include <cuda_runtime.h>
#include <cuda_fp16.h>
#include <cstdint>

// ============================================================
// Problem constants
// ============================================================
#define NUM_E     8
#define DIM_H     1024
#define DIM_F     4096
#define TOK_TOTAL 16384
#define TOK_PER_E 2048

// GEMM tiling: CTA 128x128, 8 warps of 64x32, 3-stage pipeline, 2 CTA/SM
#define STAGES  3
#define KT      64             // k halves per stage (= 128 bytes/row)
#define MT      128
#define NT      128

#define A_STRIDE_H      72     // halves per smem row (64 data + 8 pad = 144B) -> conflict-free
#define A_STAGE_HALFS   (MT * A_STRIDE_H)        // 9216
#define B_STAGE_HALFS   (NT * A_STRIDE_H)        // 9216
#define STAGE_HALFS     (A_STAGE_HALFS + B_STAGE_HALFS)
#define SMEM_ALLOC      (STAGES * STAGE_HALFS * 2)   // 110592 bytes

// ============================================================
// Scratch (__device__ globals — allocation-free rule)
// ============================================================
__device__ __half g_xh[(size_t)TOK_TOTAL * DIM_H];         //  32 MB  x (fp16)
__device__ __half g_w1t[(size_t)NUM_E * DIM_F * DIM_H];    //  64 MB  w1^T [e][f][h] fp16
__device__ __half g_w2t[(size_t)NUM_E * DIM_H * DIM_F];    //  64 MB  w2^T [e][h][f] fp16
__device__ __half g_inter[(size_t)TOK_TOTAL * DIM_F];      // 128 MB  gelu(x@w1) fp16

// ============================================================
// Helpers (baseline PTX only — no tcgen05 on this toolchain)
// ============================================================
__device__ __forceinline__ uint32_t smem_to_u32(const void* smem_ptr) {
    uint32_t addr;
    asm("{ .reg .u64 tmp; cvta.to.shared.u64 tmp, %1; cvt.u32.u64 %0, tmp; }"
        : "=r"(addr) : "l"(smem_ptr));
    return addr;
}

__device__ __forceinline__ void cp_async16(uint32_t smem_addr, const void* gptr) {
    asm volatile("cp.async.cg.shared.global [%0], [%1], 16;"
                 :: "r"(smem_addr), "l"(gptr));
}
#define CP_ASYNC_COMMIT() asm volatile("cp.async.commit_group;" ::: "memory")
template <int N>
__device__ __forceinline__ void cp_async_wait_group() {
    asm volatile("cp.async.wait_group %0;" :: "n"(N) : "memory");
}

// mma.sync m16n8k16 fp16 -> f32 accumulate (sm_80+ baseline PTX)
__device__ __forceinline__ void mma_f16(float (&d)[4],
                                        const uint32_t (&a)[4],
                                        const uint32_t (&b)[2]) {
    asm volatile(
        "mma.sync.aligned.m16n8k16.row.col.f32.f16.f16.f32 "
        "{%0,%1,%2,%3}, {%4,%5,%6,%7}, {%8,%9}, {%0,%1,%2,%3};"
        : "+f"(d[0]), "+f"(d[1]), "+f"(d[2]), "+f"(d[3])
        : "r"(a[0]), "r"(a[1]), "r"(a[2]), "r"(a[3]),
          "r"(b[0]), "r"(b[1]));
}

__device__ __forceinline__ float gelu_tanh(float x) {
    float x3 = x * x * x;
    float t  = tanhf(0.7978845608028654f * (x + 0.044715f * x3));
    return 0.5f * x * (1.0f + t);
}

// ============================================================
// Prep kernels: fp32 -> fp16 (RN), plus K-major transposes
// ============================================================
__global__ void convert_h_kernel(const float* __restrict__ in, __half* __restrict__ out, int n)
{
    for (int i = blockIdx.x * blockDim.x + threadIdx.x; i < n; i += gridDim.x * blockDim.x)
        out[i] = __float2half_rn(in[i]);
}

// in: [E][R][C] fp32 -> out: [E][C][R] fp16
__global__ void transpose_h_kernel(const float* __restrict__ in, __half* __restrict__ out,
                                   int R, int C)
{
    __shared__ float tile[32][33];
    const int e  = blockIdx.z;
    const int c0 = blockIdx.x << 5;
    const int r0 = blockIdx.y << 5;
    const float* ine  = in  + (size_t)e * R * C;
    __half*      oute = out + (size_t)e * R * C;
    const int tx = threadIdx.x, ty = threadIdx.y;   // 32 x 8
#pragma unroll
    for (int dy = 0; dy < 32; dy += 8)
        tile[ty + dy][tx] = ine[(size_t)(r0 + ty + dy) * C + c0 + tx];
    __syncthreads();
#pragma unroll
    for (int dy = 0; dy < 32; dy += 8)
        oute[(size_t)(c0 + ty + dy) * R + r0 + tx] = __float2half_rn(tile[tx][ty + dy]);
}

// ============================================================
// Grouped fp16 GEMM:  C[e] (+gelu) = A[e] @ B[e]^T
//   A: [Mtot, K] K-major fp16;  B: [Ntot, K] K-major fp16
//   C: fp16 (when do_gelu, -> inter) or fp32 (final output)
// CTA: 128x128, 8 warps of 64x32, KT=64, 3-stage cp.async, 2 CTA/SM.
// ============================================================
__global__ void __launch_bounds__(256, 2) gemm_f16_kernel(
    const __half* __restrict__ A, int lda, long sAe,
    const __half* __restrict__ B, int ldb, long sBe,
    void* __restrict__ Cv, int ldc, long sCe,
    int K, int n_tiles, int do_gelu)
{
    extern __shared__ __half smemh[];

    const int tid = threadIdx.x;
    const int wid = tid >> 5;
    const int lid = tid & 31;
    const int g   = lid >> 2;      // groupID (0..7)
    const int tig = lid & 3;       // thread in group (0..3)
    const int wm  = (wid & 1) * 64;      // 2 warps across M
    const int wn  = (wid >> 1) * 32;     // 4 warps across N

    const int e  = blockIdx.y;
    const int mt = blockIdx.x / n_tiles;
    const int nt = blockIdx.x - mt * n_tiles;

    const __half* Ab = A + (size_t)e * sAe + (size_t)mt * MT * lda;
    const __half* Bb = B + (size_t)e * sBe + (size_t)nt * NT * ldb;

    float acc[4][4][4];                  // [mfrag][nfrag][quad]
#pragma unroll
    for (int f = 0; f < 4; f++)
#pragma unroll
        for (int j = 0; j < 4; j++)
#pragma unroll
            for (int q = 0; q < 4; q++) acc[f][j][q] = 0.0f;

    // ---------------- stage loader ----------------
    // A: 128 rows x 128 bytes = 1024 16B chunks, 4/thread; B same.
    auto load_stage = [&](int buf, int k0) {
        __half* as_ = smemh + buf * STAGE_HALFS;
#pragma unroll
        for (int t = 0; t < 4; t++) {
            int idx = tid + t * 256;
            int r = idx >> 3, c = idx & 7;
            cp_async16(smem_to_u32(as_ + r * A_STRIDE_H + c * 8),
                       Ab + (size_t)r * lda + k0 + c * 8);
        }
        __half* bs_ = as_ + A_STAGE_HALFS;
#pragma unroll
        for (int t = 0; t < 4; t++) {
            int idx = tid + t * 256;
            int r = idx >> 3, c = idx & 7;
            cp_async16(smem_to_u32(bs_ + r * A_STRIDE_H + c * 8),
                       Bb + (size_t)r * ldb + k0 + c * 8);
        }
    };

    const int NK = K / KT;

    // prologue: fill stages 0..STAGES-2
#pragma unroll
    for (int s = 0; s < STAGES - 1; s++) {
        load_stage(s, s * KT);
        CP_ASYNC_COMMIT();
    }

    int buf = 0;
    for (int i = 0; i < NK; i++) {
        cp_async_wait_group<STAGES - 2>();
        __syncthreads();

        // issue next stage's loads into the buffer consumed last iteration
        const int jn = i + STAGES - 1;
        int nbuf = buf + 1; if (nbuf == STAGES) nbuf = 0;
        if (jn < NK) {
            int lbuf = buf - 1; if (lbuf < 0) lbuf += STAGES;
            load_stage(lbuf, jn * KT);
        }
        CP_ASYNC_COMMIT();

        // compute on stage `buf`: 4 k-slices of k16
        const __half* As = smemh + buf * STAGE_HALFS;
        const __half* Bs = As + A_STAGE_HALFS;
#pragma unroll
        for (int kk = 0; kk < KT / 16; kk++) {
            const int k0 = kk * 16 + 2 * tig;   // halves
            uint32_t a[4][4];
#pragma unroll
            for (int f = 0; f < 4; f++) {
                const __half* ap = As + (wm + 16 * f + g) * A_STRIDE_H + k0;
                a[f][0] = *reinterpret_cast<const uint32_t*>(ap);
                a[f][1] = *reinterpret_cast<const uint32_t*>(ap + 8 * A_STRIDE_H);
                a[f][2] = *reinterpret_cast<const uint32_t*>(ap + 8);
                a[f][3] = *reinterpret_cast<const uint32_t*>(ap + 8 * A_STRIDE_H + 8);
            }
            uint32_t b[4][2];
#pragma unroll
            for (int j = 0; j < 4; j++) {
                const __half* bp = Bs + (wn + 8 * j + g) * A_STRIDE_H + k0;
                b[j][0] = *reinterpret_cast<const uint32_t*>(bp);
                b[j][1] = *reinterpret_cast<const uint32_t*>(bp + 8);
            }
#pragma unroll
            for (int f = 0; f < 4; f++)
#pragma unroll
                for (int j = 0; j < 4; j++)
                    mma_f16(acc[f][j], a[f], b[j]);
        }
        buf = nbuf;
    }

    // ---------------- epilogue ----------------
    if (do_gelu) {
        __half* Cb = (__half*)Cv + (size_t)e * sCe + (size_t)mt * MT * ldc + (size_t)nt * NT;
#pragma unroll
        for (int f = 0; f < 4; f++) {
            const int r0 = wm + 16 * f + g;
            const int r1 = r0 + 8;
#pragma unroll
            for (int j = 0; j < 4; j++) {
                const int col = wn + 8 * j + 2 * tig;
                __half2 p0 = __floats2half2_rn(gelu_tanh(acc[f][j][0]),
                                               gelu_tanh(acc[f][j][1]));
                __half2 p1 = __floats2half2_rn(gelu_tanh(acc[f][j][2]),
                                               gelu_tanh(acc[f][j][3]));
                *reinterpret_cast<__half2*>(Cb + (size_t)r0 * ldc + col) = p0;
                *reinterpret_cast<__half2*>(Cb + (size_t)r1 * ldc + col) = p1;
            }
        }
    } else {
        float* Cb = (float*)Cv + (size_t)e * sCe + (size_t)mt * MT * ldc + (size_t)nt * NT;
#pragma unroll
        for (int f = 0; f < 4; f++) {
            const int r0 = wm + 16 * f + g;
            const int r1 = r0 + 8;
#pragma unroll
            for (int j = 0; j < 4; j++) {
                const int col = wn + 8 * j + 2 * tig;
                *reinterpret_cast<float2*>(Cb + (size_t)r0 * ldc + col) =
                    make_float2(acc[f][j][0], acc[f][j][1]);
                *reinterpret_cast<float2*>(Cb + (size_t)r1 * ldc + col) =
                    make_float2(acc[f][j][2], acc[f][j][3]);
            }
        }
    }
}

// ============================================================
// Host launcher
// ============================================================
extern "C" void kernel_launch(void* const* d_in, const int* in_sizes, int n_in,
                              void* d_out, int out_size)
{
    const float* x  = (const float*)d_in[0];
    const float* w1 = (const float*)d_in[1];
    const float* w2 = (const float*)d_in[2];
    float* out = (float*)d_out;

    __half *xh, *w1t, *w2t, *inter;
    cudaGetSymbolAddress((void**)&xh,    g_xh);
    cudaGetSymbolAddress((void**)&w1t,   g_w1t);
    cudaGetSymbolAddress((void**)&w2t,   g_w2t);
    cudaGetSymbolAddress((void**)&inter, g_inter);

    cudaFuncSetAttribute(gemm_f16_kernel,
                         cudaFuncAttributeMaxDynamicSharedMemorySize, SMEM_ALLOC);

    // prep: fp16 conversion + weight transposes to K-major
    convert_h_kernel<<<2048, 256>>>(x, xh, TOK_TOTAL * DIM_H);
    transpose_h_kernel<<<dim3(DIM_F / 32, DIM_H / 32, NUM_E), dim3(32, 8)>>>(
        w1, w1t, DIM_H, DIM_F);   // [E][H][F] -> [E][F][H]
    transpose_h_kernel<<<dim3(DIM_H / 32, DIM_F / 32, NUM_E), dim3(32, 8)>>>(
        w2, w2t, DIM_F, DIM_H);   // [E][F][H] -> [E][H][F]

    // GEMM1: inter = gelu(x @ w1^T_kmajor)   (M=2048/expert, N=4096, K=1024), fp16 out
    gemm_f16_kernel<<<dim3((TOK_PER_E / MT) * (DIM_F / NT), NUM_E), 256, SMEM_ALLOC>>>(
        xh,    DIM_H, (long)TOK_PER_E * DIM_H,
        w1t,   DIM_H, (long)DIM_F * DIM_H,
        inter, DIM_F, (long)TOK_PER_E * DIM_F,
        DIM_H, DIM_F / NT, /*gelu=*/1);

    // GEMM2: out = inter @ w2^T_kmajor       (M=2048/expert, N=1024, K=4096), fp32 out
    gemm_f16_kernel<<<dim3((TOK_PER_E / MT) * (DIM_H / NT), NUM_E), 256, SMEM_ALLOC>>>(
        inter, DIM_F, (long)TOK_PER_E * DIM_F,
        w2t,   DIM_F, (long)DIM_H * DIM_F,
        out,   DIM_H, (long)TOK_PER_E * DIM_H,
        DIM_F, DIM_H / NT, /*gelu=*/0);
}

// round 9
// speedup vs baseline: 2.1465x; 1.1101x over previous
#include <cuda_runtime.h>
#include <cuda_fp16.h>
#include <cstdint>

// ============================================================
// Problem constants
// ============================================================
#define NUM_E     8
#define DIM_H     1024
#define DIM_F     4096
#define TOK_TOTAL 16384
#define TOK_PER_E 2048

// GEMM tiling: CTA 128x128, 8 warps of 64x32, 3-stage pipeline, 2 CTA/SM
#define STAGES  3
#define KT      64             // k halves per stage (= 128 bytes/row)
#define MT      128
#define NT      128

#define A_STRIDE_H      72     // halves per smem row (64 data + 8 pad = 144B) -> conflict-free
#define ROW_B           144    // row bytes
#define A_STAGE_HALFS   (MT * A_STRIDE_H)        // 9216
#define B_STAGE_HALFS   (NT * A_STRIDE_H)        // 9216
#define STAGE_HALFS     (A_STAGE_HALFS + B_STAGE_HALFS)
#define STAGE_BYTES     (STAGE_HALFS * 2)        // 36864
#define A_STAGE_BYTES   (A_STAGE_HALFS * 2)      // 18432
#define SMEM_ALLOC      (STAGES * STAGE_BYTES)   // 110592 bytes

// ============================================================
// Scratch (__device__ globals — allocation-free rule)
// ============================================================
__device__ __half g_xh[(size_t)TOK_TOTAL * DIM_H];         //  32 MB  x (fp16)
__device__ __half g_w1t[(size_t)NUM_E * DIM_F * DIM_H];    //  64 MB  w1^T [e][f][h] fp16
__device__ __half g_w2t[(size_t)NUM_E * DIM_H * DIM_F];    //  64 MB  w2^T [e][h][f] fp16
__device__ __half g_inter[(size_t)TOK_TOTAL * DIM_F];      // 128 MB  gelu(x@w1) fp16

// ============================================================
// Helpers (baseline PTX only — no tcgen05 on this toolchain)
// ============================================================
__device__ __forceinline__ uint32_t smem_to_u32(const void* smem_ptr) {
    uint32_t addr;
    asm("{ .reg .u64 tmp; cvta.to.shared.u64 tmp, %1; cvt.u32.u64 %0, tmp; }"
        : "=r"(addr) : "l"(smem_ptr));
    return addr;
}

__device__ __forceinline__ void cp_async16(uint32_t smem_addr, const void* gptr) {
    asm volatile("cp.async.cg.shared.global [%0], [%1], 16;"
                 :: "r"(smem_addr), "l"(gptr));
}
#define CP_ASYNC_COMMIT() asm volatile("cp.async.commit_group;" ::: "memory")
template <int N>
__device__ __forceinline__ void cp_async_wait_group() {
    asm volatile("cp.async.wait_group %0;" :: "n"(N) : "memory");
}

// ldmatrix x4: four 8x8 b16 tiles
__device__ __forceinline__ void ldsm_x4(uint32_t (&d)[4], uint32_t addr) {
    asm volatile("ldmatrix.sync.aligned.m8n8.x4.shared.b16 {%0,%1,%2,%3}, [%4];"
                 : "=r"(d[0]), "=r"(d[1]), "=r"(d[2]), "=r"(d[3]) : "r"(addr));
}

// mma.sync m16n8k16 fp16 -> f32 accumulate (sm_80+ baseline PTX)
__device__ __forceinline__ void mma_f16(float (&d)[4],
                                        const uint32_t (&a)[4],
                                        uint32_t b0, uint32_t b1) {
    asm volatile(
        "mma.sync.aligned.m16n8k16.row.col.f32.f16.f16.f32 "
        "{%0,%1,%2,%3}, {%4,%5,%6,%7}, {%8,%9}, {%0,%1,%2,%3};"
        : "+f"(d[0]), "+f"(d[1]), "+f"(d[2]), "+f"(d[3])
        : "r"(a[0]), "r"(a[1]), "r"(a[2]), "r"(a[3]),
          "r"(b0), "r"(b1));
}

__device__ __forceinline__ float gelu_tanh(float x) {
    float x3 = x * x * x;
    float t  = tanhf(0.7978845608028654f * (x + 0.044715f * x3));
    return 0.5f * x * (1.0f + t);
}

// ============================================================
// Prep kernels: fp32 -> fp16 (RN), plus K-major transposes
// ============================================================
__global__ void convert_h_kernel(const float* __restrict__ in, __half* __restrict__ out, int n)
{
    for (int i = blockIdx.x * blockDim.x + threadIdx.x; i < n; i += gridDim.x * blockDim.x)
        out[i] = __float2half_rn(in[i]);
}

// in: [E][R][C] fp32 -> out: [E][C][R] fp16
__global__ void transpose_h_kernel(const float* __restrict__ in, __half* __restrict__ out,
                                   int R, int C)
{
    __shared__ float tile[32][33];
    const int e  = blockIdx.z;
    const int c0 = blockIdx.x << 5;
    const int r0 = blockIdx.y << 5;
    const float* ine  = in  + (size_t)e * R * C;
    __half*      oute = out + (size_t)e * R * C;
    const int tx = threadIdx.x, ty = threadIdx.y;   // 32 x 8
#pragma unroll
    for (int dy = 0; dy < 32; dy += 8)
        tile[ty + dy][tx] = ine[(size_t)(r0 + ty + dy) * C + c0 + tx];
    __syncthreads();
#pragma unroll
    for (int dy = 0; dy < 32; dy += 8)
        oute[(size_t)(c0 + ty + dy) * R + r0 + tx] = __float2half_rn(tile[tx][ty + dy]);
}

// ============================================================
// Grouped fp16 GEMM:  C[e] (+gelu) = A[e] @ B[e]^T
//   A: [Mtot, K] K-major fp16;  B: [Ntot, K] K-major fp16
//   C: fp16 (when do_gelu, -> inter) or fp32 (final output)
// CTA: 128x128, 8 warps of 64x32, KT=64, 3-stage cp.async, 2 CTA/SM,
// ldmatrix.x4 fragment loads (native fp16 layout).
// ============================================================
__global__ void __launch_bounds__(256, 2) gemm_f16_kernel(
    const __half* __restrict__ A, int lda, long sAe,
    const __half* __restrict__ B, int ldb, long sBe,
    void* __restrict__ Cv, int ldc, long sCe,
    int K, int n_tiles, int do_gelu)
{
    extern __shared__ __half smemh[];
    const uint32_t smem_base = smem_to_u32(smemh);

    const int tid = threadIdx.x;
    const int wid = tid >> 5;
    const int lid = tid & 31;
    const int g   = lid >> 2;      // groupID (0..7)
    const int tig = lid & 3;       // thread in group (0..3)
    const int wm  = (wid & 1) * 64;      // 2 warps across M
    const int wn  = (wid >> 1) * 32;     // 4 warps across N

    const int e  = blockIdx.y;
    const int mt = blockIdx.x / n_tiles;
    const int nt = blockIdx.x - mt * n_tiles;

    const __half* Ab = A + (size_t)e * sAe + (size_t)mt * MT * lda;
    const __half* Bb = B + (size_t)e * sBe + (size_t)nt * NT * ldb;

    float acc[4][4][4];                  // [mfrag][nfrag][quad]
#pragma unroll
    for (int f = 0; f < 4; f++)
#pragma unroll
        for (int j = 0; j < 4; j++)
#pragma unroll
            for (int q = 0; q < 4; q++) acc[f][j][q] = 0.0f;

    // per-lane ldmatrix offsets (bytes, within a stage buffer):
    // A x4 tiles: [r0-7,k0-7],[r8-15,k0-7],[r0-7,k8-15],[r8-15,k8-15]
    //   lanes 0-15 -> rows 0-15 @k0; lanes 16-31 -> rows 0-15 @k8 (+16B)
    const uint32_t a_loff = (uint32_t)(wm * ROW_B + (lid & 15) * ROW_B + (lid >> 4) * 16);
    // B x4 tiles: [n0-7,k0-7],[n0-7,k8-15],[n8-15,k0-7],[n8-15,k8-15]
    //   lanes: bit3 -> +16B (k8), bit4 -> +8 rows
    const uint32_t b_loff = (uint32_t)(A_STAGE_BYTES + wn * ROW_B + (lid & 7) * ROW_B
                                       + ((lid >> 3) & 1) * 16 + (lid >> 4) * (8 * ROW_B));

    // ---------------- stage loader ----------------
    // A: 128 rows x 128 bytes = 1024 16B chunks, 4/thread; B same.
    auto load_stage = [&](int buf, int k0) {
        __half* as_ = smemh + buf * STAGE_HALFS;
#pragma unroll
        for (int t = 0; t < 4; t++) {
            int idx = tid + t * 256;
            int r = idx >> 3, c = idx & 7;
            cp_async16(smem_to_u32(as_ + r * A_STRIDE_H + c * 8),
                       Ab + (size_t)r * lda + k0 + c * 8);
        }
        __half* bs_ = as_ + A_STAGE_HALFS;
#pragma unroll
        for (int t = 0; t < 4; t++) {
            int idx = tid + t * 256;
            int r = idx >> 3, c = idx & 7;
            cp_async16(smem_to_u32(bs_ + r * A_STRIDE_H + c * 8),
                       Bb + (size_t)r * ldb + k0 + c * 8);
        }
    };

    const int NK = K / KT;

    // prologue: fill stages 0..STAGES-2
#pragma unroll
    for (int s = 0; s < STAGES - 1; s++) {
        load_stage(s, s * KT);
        CP_ASYNC_COMMIT();
    }

    int buf = 0;
    for (int i = 0; i < NK; i++) {
        cp_async_wait_group<STAGES - 2>();
        __syncthreads();

        // issue next stage's loads into the buffer consumed last iteration
        const int jn = i + STAGES - 1;
        int nbuf = buf + 1; if (nbuf == STAGES) nbuf = 0;
        if (jn < NK) {
            int lbuf = buf - 1; if (lbuf < 0) lbuf += STAGES;
            load_stage(lbuf, jn * KT);
        }
        CP_ASYNC_COMMIT();

        // compute on stage `buf`: 4 k-slices of k16, LDSM fragment loads
        const uint32_t sa = smem_base + buf * STAGE_BYTES;
#pragma unroll
        for (int kk = 0; kk < KT / 16; kk++) {
            const uint32_t koff = sa + kk * 32;
            uint32_t a[4][4];
#pragma unroll
            for (int f = 0; f < 4; f++)
                ldsm_x4(a[f], koff + a_loff + f * (16 * ROW_B));
            uint32_t bb[2][4];   // bb[p] = {j(2p).b0, j(2p).b1, j(2p+1).b0, j(2p+1).b1}
#pragma unroll
            for (int p = 0; p < 2; p++)
                ldsm_x4(bb[p], koff + b_loff + p * (16 * ROW_B));
#pragma unroll
            for (int f = 0; f < 4; f++)
#pragma unroll
                for (int j = 0; j < 4; j++)
                    mma_f16(acc[f][j], a[f],
                            bb[j >> 1][(j & 1) * 2], bb[j >> 1][(j & 1) * 2 + 1]);
        }
        buf = nbuf;
    }

    // ---------------- epilogue ----------------
    if (do_gelu) {
        __half* Cb = (__half*)Cv + (size_t)e * sCe + (size_t)mt * MT * ldc + (size_t)nt * NT;
#pragma unroll
        for (int f = 0; f < 4; f++) {
            const int r0 = wm + 16 * f + g;
            const int r1 = r0 + 8;
#pragma unroll
            for (int j = 0; j < 4; j++) {
                const int col = wn + 8 * j + 2 * tig;
                __half2 p0 = __floats2half2_rn(gelu_tanh(acc[f][j][0]),
                                               gelu_tanh(acc[f][j][1]));
                __half2 p1 = __floats2half2_rn(gelu_tanh(acc[f][j][2]),
                                               gelu_tanh(acc[f][j][3]));
                *reinterpret_cast<__half2*>(Cb + (size_t)r0 * ldc + col) = p0;
                *reinterpret_cast<__half2*>(Cb + (size_t)r1 * ldc + col) = p1;
            }
        }
    } else {
        float* Cb = (float*)Cv + (size_t)e * sCe + (size_t)mt * MT * ldc + (size_t)nt * NT;
#pragma unroll
        for (int f = 0; f < 4; f++) {
            const int r0 = wm + 16 * f + g;
            const int r1 = r0 + 8;
#pragma unroll
            for (int j = 0; j < 4; j++) {
                const int col = wn + 8 * j + 2 * tig;
                *reinterpret_cast<float2*>(Cb + (size_t)r0 * ldc + col) =
                    make_float2(acc[f][j][0], acc[f][j][1]);
                *reinterpret_cast<float2*>(Cb + (size_t)r1 * ldc + col) =
                    make_float2(acc[f][j][2], acc[f][j][3]);
            }
        }
    }
}

// ============================================================
// Host launcher
// ============================================================
extern "C" void kernel_launch(void* const* d_in, const int* in_sizes, int n_in,
                              void* d_out, int out_size)
{
    const float* x  = (const float*)d_in[0];
    const float* w1 = (const float*)d_in[1];
    const float* w2 = (const float*)d_in[2];
    float* out = (float*)d_out;

    __half *xh, *w1t, *w2t, *inter;
    cudaGetSymbolAddress((void**)&xh,    g_xh);
    cudaGetSymbolAddress((void**)&w1t,   g_w1t);
    cudaGetSymbolAddress((void**)&w2t,   g_w2t);
    cudaGetSymbolAddress((void**)&inter, g_inter);

    cudaFuncSetAttribute(gemm_f16_kernel,
                         cudaFuncAttributeMaxDynamicSharedMemorySize, SMEM_ALLOC);

    // prep: fp16 conversion + weight transposes to K-major
    convert_h_kernel<<<2048, 256>>>(x, xh, TOK_TOTAL * DIM_H);
    transpose_h_kernel<<<dim3(DIM_F / 32, DIM_H / 32, NUM_E), dim3(32, 8)>>>(
        w1, w1t, DIM_H, DIM_F);   // [E][H][F] -> [E][F][H]
    transpose_h_kernel<<<dim3(DIM_H / 32, DIM_F / 32, NUM_E), dim3(32, 8)>>>(
        w2, w2t, DIM_F, DIM_H);   // [E][F][H] -> [E][H][F]

    // GEMM1: inter = gelu(x @ w1^T_kmajor)   (M=2048/expert, N=4096, K=1024), fp16 out
    gemm_f16_kernel<<<dim3((TOK_PER_E / MT) * (DIM_F / NT), NUM_E), 256, SMEM_ALLOC>>>(
        xh,    DIM_H, (long)TOK_PER_E * DIM_H,
        w1t,   DIM_H, (long)DIM_F * DIM_H,
        inter, DIM_F, (long)TOK_PER_E * DIM_F,
        DIM_H, DIM_F / NT, /*gelu=*/1);

    // GEMM2: out = inter @ w2^T_kmajor       (M=2048/expert, N=1024, K=4096), fp32 out
    gemm_f16_kernel<<<dim3((TOK_PER_E / MT) * (DIM_H / NT), NUM_E), 256, SMEM_ALLOC>>>(
        inter, DIM_F, (long)TOK_PER_E * DIM_F,
        w2t,   DIM_F, (long)DIM_H * DIM_F,
        out,   DIM_H, (long)TOK_PER_E * DIM_H,
        DIM_F, DIM_H / NT, /*gelu=*/0);
}